// round 1
// baseline (speedup 1.0000x reference)
#include <cuda_runtime.h>
#include <math.h>

// Problem constants
#define TT   512
#define BB   64
#define INN  512
#define HH   1024
#define G4   4096   // 4*HH

// Scratch (allocation-free rule: static __device__ globals)
__device__ float g_xproj[(size_t)TT * BB * G4];   // [T*B][4H]  x @ W_ih^T + (b_ih+b_hh)
__device__ float g_c[BB * HH];                    // cell state, rewritten each replay

// ---------------------------------------------------------------------------
// Kernel 1: x projection GEMM.
// C[M=T*B][N=4H] = xs[M][IN] * W_ih[N][IN]^T + (b_ih + b_hh)
// BM=128, BN=128, BK=16, 256 threads, 8x8 thread tiles.
// ---------------------------------------------------------------------------
__global__ __launch_bounds__(256, 2)
void xproj_kernel(const float* __restrict__ xs,
                  const float* __restrict__ Wih,
                  const float* __restrict__ bih,
                  const float* __restrict__ bhh)
{
    const int BM = 128, BN = 128, BK = 16;
    __shared__ float As[BK][BM];
    __shared__ float Bs[BK][BN];

    const int tid = threadIdx.x;
    const int tx  = tid & 15;      // 0..15 -> N
    const int ty  = tid >> 4;      // 0..15 -> M
    const int rm  = blockIdx.y;    // M tile (256)
    const int cn  = blockIdx.x;    // N tile (32)

    const float* Ab = xs  + (size_t)rm * BM * INN;
    const float* Bb = Wih + (size_t)cn * BN * INN;

    float acc[8][8];
#pragma unroll
    for (int i = 0; i < 8; i++)
#pragma unroll
        for (int j = 0; j < 8; j++) acc[i][j] = 0.0f;

    const int lr = tid >> 2;         // 0..63 row
    const int lc = (tid & 3) * 4;    // 0,4,8,12 k offset

    for (int k0 = 0; k0 < INN; k0 += BK) {
#pragma unroll
        for (int rr = 0; rr < 2; rr++) {
            const int row = lr + rr * 64;
            float4 va = *(const float4*)(Ab + (size_t)row * INN + k0 + lc);
            As[lc + 0][row] = va.x; As[lc + 1][row] = va.y;
            As[lc + 2][row] = va.z; As[lc + 3][row] = va.w;
            float4 vb = *(const float4*)(Bb + (size_t)row * INN + k0 + lc);
            Bs[lc + 0][row] = vb.x; Bs[lc + 1][row] = vb.y;
            Bs[lc + 2][row] = vb.z; Bs[lc + 3][row] = vb.w;
        }
        __syncthreads();

#pragma unroll
        for (int k = 0; k < BK; k++) {
            float ra[8], rb[8];
            *(float4*)(ra)     = *(const float4*)&As[k][ty * 8];
            *(float4*)(ra + 4) = *(const float4*)&As[k][ty * 8 + 4];
            *(float4*)(rb)     = *(const float4*)&Bs[k][tx * 8];
            *(float4*)(rb + 4) = *(const float4*)&Bs[k][tx * 8 + 4];
#pragma unroll
            for (int i = 0; i < 8; i++)
#pragma unroll
                for (int j = 0; j < 8; j++)
                    acc[i][j] += ra[i] * rb[j];
        }
        __syncthreads();
    }

    // bias for this thread's 8 output columns
    const int ncol0 = cn * BN + tx * 8;
    float bv[8];
#pragma unroll
    for (int j = 0; j < 8; j++) bv[j] = bih[ncol0 + j] + bhh[ncol0 + j];

#pragma unroll
    for (int i = 0; i < 8; i++) {
        const size_t row = (size_t)rm * BM + ty * 8 + i;
        float* outp = g_xproj + row * G4 + ncol0;
        float4 o0, o1;
        o0.x = acc[i][0] + bv[0]; o0.y = acc[i][1] + bv[1];
        o0.z = acc[i][2] + bv[2]; o0.w = acc[i][3] + bv[3];
        o1.x = acc[i][4] + bv[4]; o1.y = acc[i][5] + bv[5];
        o1.z = acc[i][6] + bv[6]; o1.w = acc[i][7] + bv[7];
        *(float4*)(outp)     = o0;
        *(float4*)(outp + 4) = o1;
    }
}

// ---------------------------------------------------------------------------
// Kernel 2: one LSTM step.
// Block bid owns 8 hidden units n0..n0+7 (all 4 gates, all 64 batches).
// GEMM tile: C[64 batch][32 gatecols] = h_prev[64][1024] * Wsel[1024][32],
//   gatecol = g*8 + u  ->  W_hh row = g*H + n0 + u.
// Then fused: gates += xproj[t], nonlinearities, c/h update, h -> d_out[t].
// grid = 128 blocks, 256 threads.
// ---------------------------------------------------------------------------
__global__ __launch_bounds__(256, 1)
void step_kernel(int t,
                 const float* __restrict__ hprev,   // [B][H] (h0 or d_out[t-1])
                 const float* __restrict__ c0,      // [B][H]
                 const float* __restrict__ Whh,     // [4H][H]
                 float* __restrict__ out)           // [T][B][H]
{
    const int BK = 32;
    __shared__ float Hs[64][36];   // stride 36: 16B-aligned rows, rotated banks
    __shared__ float Ws[32][36];
    __shared__ float Gs[64][33];

    const int tid = threadIdx.x;
    const int tx  = tid & 15;      // 0..15 -> 2 cols each
    const int ty  = tid >> 4;      // 0..15 -> 4 rows each
    const int n0  = blockIdx.x * 8;

    float acc[4][2];
#pragma unroll
    for (int r = 0; r < 4; r++) { acc[r][0] = 0.0f; acc[r][1] = 0.0f; }

    // global->smem mapping
    const int hb = tid >> 3;            // 0..31 (batch row, +32 second half)
    const int hk = (tid & 7) * 4;       // k offset within tile
    const int wc = tid >> 3;            // 0..31 gate col
    const int wrow = (wc >> 3) * HH + n0 + (wc & 7);

    for (int k0 = 0; k0 < HH; k0 += BK) {
        float4 v0 = *(const float4*)(hprev + (size_t)hb * HH + k0 + hk);
        float4 v1 = *(const float4*)(hprev + (size_t)(hb + 32) * HH + k0 + hk);
        *(float4*)&Hs[hb][hk]      = v0;
        *(float4*)&Hs[hb + 32][hk] = v1;
        float4 w = *(const float4*)(Whh + (size_t)wrow * HH + k0 + hk);
        *(float4*)&Ws[wc][hk] = w;
        __syncthreads();

#pragma unroll
        for (int k4 = 0; k4 < BK; k4 += 4) {
            float4 wv0 = *(const float4*)&Ws[tx * 2 + 0][k4];
            float4 wv1 = *(const float4*)&Ws[tx * 2 + 1][k4];
#pragma unroll
            for (int r = 0; r < 4; r++) {
                float4 hv = *(const float4*)&Hs[ty * 4 + r][k4];
                acc[r][0] += hv.x * wv0.x + hv.y * wv0.y + hv.z * wv0.z + hv.w * wv0.w;
                acc[r][1] += hv.x * wv1.x + hv.y * wv1.y + hv.z * wv1.z + hv.w * wv1.w;
            }
        }
        __syncthreads();
    }

    // stash gate tile to smem so each (b,u) thread can gather its 4 gates
#pragma unroll
    for (int r = 0; r < 4; r++) {
        Gs[ty * 4 + r][tx * 2 + 0] = acc[r][0];
        Gs[ty * 4 + r][tx * 2 + 1] = acc[r][1];
    }
    __syncthreads();

    const float* xp = g_xproj + (size_t)t * BB * G4;

#pragma unroll
    for (int pp = 0; pp < 2; pp++) {
        const int p = tid + pp * 256;      // 0..511 -> (b,u)
        const int b = p >> 3;
        const int u = p & 7;
        const size_t xbase = (size_t)b * G4 + n0 + u;

        float gi = Gs[b][u]      + xp[xbase];
        float gf = Gs[b][8 + u]  + xp[xbase + HH];
        float gg = Gs[b][16 + u] + xp[xbase + 2 * HH];
        float go = Gs[b][24 + u] + xp[xbase + 3 * HH];

        const float ii = 1.0f / (1.0f + expf(-gi));
        const float ff = 1.0f / (1.0f + expf(-gf));
        const float g2 = tanhf(gg);
        const float oo = 1.0f / (1.0f + expf(-go));

        const int cidx = b * HH + n0 + u;
        const float cprev = (t == 0) ? c0[cidx] : g_c[cidx];
        const float cnew = ff * cprev + ii * g2;
        g_c[cidx] = cnew;

        out[(size_t)t * BB * HH + cidx] = oo * tanhf(cnew);
    }
}

// ---------------------------------------------------------------------------
// Launch: 1 xproj GEMM + 512 sequential step kernels (graph-capturable).
// ---------------------------------------------------------------------------
extern "C" void kernel_launch(void* const* d_in, const int* in_sizes, int n_in,
                              void* d_out, int out_size)
{
    const float* xs  = (const float*)d_in[0];   // [T,B,IN]
    const float* h0  = (const float*)d_in[1];   // [B,H]
    const float* c0  = (const float*)d_in[2];   // [B,H]
    const float* Wih = (const float*)d_in[3];   // [4H,IN]
    const float* Whh = (const float*)d_in[4];   // [4H,H]
    const float* bih = (const float*)d_in[5];   // [4H]
    const float* bhh = (const float*)d_in[6];   // [4H]
    float* out = (float*)d_out;                 // [T,B,H]

    (void)in_sizes; (void)n_in; (void)out_size;

    dim3 grid1(G4 / 128, (TT * BB) / 128);      // 32 x 256
    xproj_kernel<<<grid1, 256>>>(xs, Wih, bih, bhh);

    for (int t = 0; t < TT; t++) {
        const float* hprev = (t == 0) ? h0 : (out + (size_t)(t - 1) * BB * HH);
        step_kernel<<<HH / 8, 256>>>(t, hprev, c0, Whh, out);
    }
}

// round 4
// speedup vs baseline: 2.2597x; 2.2597x over previous
#include <cuda_runtime.h>
#include <cuda_bf16.h>
#include <stdint.h>
#include <math.h>

// Problem constants
#define TT   512
#define BB   64
#define INN  512
#define HH   1024
#define G4   4096   // 4*HH

// Step-GEMM tiling: 128 CTAs, each M=32 gate rows (4 gates x 8 units), N=64, K=1024
#define NCTA2  128
#define KC     64
#define NCHUNK 16      // 1024/64
#define NSTAGE 4

// smem stage layout (bytes). Rows padded to 72 bf16 (144 B) to rotate banks for ldmatrix.
#define AHI  0
#define ALO  4608      // 32*144
#define BHI  9216
#define BLO  18432     // + 64*144
#define SSTG 27648     // per stage
#define SMEM_REQ (NSTAGE * SSTG)   // 110592

// ---------------- device scratch (allocation-free rule) ----------------
__device__ float g_xproj[(size_t)TT * BB * G4];                    // [T*B][4H]
__device__ float g_c[BB * HH];                                     // cell state
__device__ __align__(16) unsigned char g_whi2[(size_t)NCTA2 * NCHUNK * 32 * 128];  // 8 MB
__device__ __align__(16) unsigned char g_wlo2[(size_t)NCTA2 * NCHUNK * 32 * 128];  // 8 MB
__device__ __align__(16) unsigned char g_hbhi[2][BB * HH * 2];     // h hi bf16 [b][k], ping-pong
__device__ __align__(16) unsigned char g_hblo[2][BB * HH * 2];     // h lo bf16 [b][k], ping-pong

// ---------------- helpers ----------------
__device__ __forceinline__ uint32_t smem_u32(const void* p) {
    uint32_t a;
    asm("{ .reg .u64 t; cvta.to.shared.u64 t, %1; cvt.u32.u64 %0, t; }" : "=r"(a) : "l"(p));
    return a;
}

__device__ __forceinline__ void split2(float a, float b, uint32_t& hi, uint32_t& lo) {
    __nv_bfloat16 ah = __float2bfloat16(a), bh = __float2bfloat16(b);
    float ar = a - __bfloat162float(ah);
    float br = b - __bfloat162float(bh);
    __nv_bfloat16 al = __float2bfloat16(ar), bl = __float2bfloat16(br);
    hi = (uint32_t)__bfloat16_as_ushort(ah) | ((uint32_t)__bfloat16_as_ushort(bh) << 16);
    lo = (uint32_t)__bfloat16_as_ushort(al) | ((uint32_t)__bfloat16_as_ushort(bl) << 16);
}

// ---------------- PTX wrappers (all baseline compute_103 features) ----------------
__device__ __forceinline__ void cpasync16(uint32_t dst, const void* src) {
    asm volatile("cp.async.cg.shared.global [%0], [%1], 16;" :: "r"(dst), "l"(src) : "memory");
}
#define CP_COMMIT() asm volatile("cp.async.commit_group;" ::: "memory")
#define CP_WAIT3()  asm volatile("cp.async.wait_group 3;" ::: "memory")

__device__ __forceinline__ void ldm4(uint32_t* r, uint32_t addr) {
    asm volatile("ldmatrix.sync.aligned.m8n8.x4.shared.b16 {%0,%1,%2,%3}, [%4];"
        : "=r"(r[0]), "=r"(r[1]), "=r"(r[2]), "=r"(r[3]) : "r"(addr));
}
__device__ __forceinline__ void mma16816(float* d, const uint32_t* a, uint32_t b0, uint32_t b1) {
    asm volatile(
        "mma.sync.aligned.m16n8k16.row.col.f32.bf16.bf16.f32 "
        "{%0,%1,%2,%3}, {%4,%5,%6,%7}, {%8,%9}, {%0,%1,%2,%3};"
        : "+f"(d[0]), "+f"(d[1]), "+f"(d[2]), "+f"(d[3])
        : "r"(a[0]), "r"(a[1]), "r"(a[2]), "r"(a[3]), "r"(b0), "r"(b1));
}

// ---------------------------------------------------------------------------
// Kernel: x projection GEMM (fp32 SIMT — proven in round 1).
// ---------------------------------------------------------------------------
__global__ __launch_bounds__(256, 2)
void xproj_kernel(const float* __restrict__ xs,
                  const float* __restrict__ Wih,
                  const float* __restrict__ bih,
                  const float* __restrict__ bhh)
{
    const int BM = 128, BN = 128, BK = 16;
    __shared__ float As[BK][BM];
    __shared__ float Bs[BK][BN];

    const int tid = threadIdx.x;
    const int tx  = tid & 15;
    const int ty  = tid >> 4;
    const int rm  = blockIdx.y;
    const int cn  = blockIdx.x;

    const float* Ab = xs  + (size_t)rm * BM * INN;
    const float* Bb = Wih + (size_t)cn * BN * INN;

    float acc[8][8];
#pragma unroll
    for (int i = 0; i < 8; i++)
#pragma unroll
        for (int j = 0; j < 8; j++) acc[i][j] = 0.0f;

    const int lr = tid >> 2;
    const int lc = (tid & 3) * 4;

    for (int k0 = 0; k0 < INN; k0 += BK) {
#pragma unroll
        for (int rr = 0; rr < 2; rr++) {
            const int row = lr + rr * 64;
            float4 va = *(const float4*)(Ab + (size_t)row * INN + k0 + lc);
            As[lc + 0][row] = va.x; As[lc + 1][row] = va.y;
            As[lc + 2][row] = va.z; As[lc + 3][row] = va.w;
            float4 vb = *(const float4*)(Bb + (size_t)row * INN + k0 + lc);
            Bs[lc + 0][row] = vb.x; Bs[lc + 1][row] = vb.y;
            Bs[lc + 2][row] = vb.z; Bs[lc + 3][row] = vb.w;
        }
        __syncthreads();

#pragma unroll
        for (int k = 0; k < BK; k++) {
            float ra[8], rb[8];
            *(float4*)(ra)     = *(const float4*)&As[k][ty * 8];
            *(float4*)(ra + 4) = *(const float4*)&As[k][ty * 8 + 4];
            *(float4*)(rb)     = *(const float4*)&Bs[k][tx * 8];
            *(float4*)(rb + 4) = *(const float4*)&Bs[k][tx * 8 + 4];
#pragma unroll
            for (int i = 0; i < 8; i++)
#pragma unroll
                for (int j = 0; j < 8; j++)
                    acc[i][j] += ra[i] * rb[j];
        }
        __syncthreads();
    }

    const int ncol0 = cn * BN + tx * 8;
    float bv[8];
#pragma unroll
    for (int j = 0; j < 8; j++) bv[j] = bih[ncol0 + j] + bhh[ncol0 + j];

#pragma unroll
    for (int i = 0; i < 8; i++) {
        const size_t row = (size_t)rm * BM + ty * 8 + i;
        float* outp = g_xproj + row * G4 + ncol0;
        float4 o0, o1;
        o0.x = acc[i][0] + bv[0]; o0.y = acc[i][1] + bv[1];
        o0.z = acc[i][2] + bv[2]; o0.w = acc[i][3] + bv[3];
        o1.x = acc[i][4] + bv[4]; o1.y = acc[i][5] + bv[5];
        o1.z = acc[i][6] + bv[6]; o1.w = acc[i][7] + bv[7];
        *(float4*)(outp)     = o0;
        *(float4*)(outp + 4) = o1;
    }
}

// ---------------------------------------------------------------------------
// Prep: split W_hh -> bf16 hi/lo, tiled per (CTA j, chunk c):
// blob[(j*16+c)][r=0..31][k=0..63], row r: gate=r>>3, unit=8j+(r&7).
// ---------------------------------------------------------------------------
__global__ __launch_bounds__(256)
void prep_w2_kernel(const float* __restrict__ Whh)
{
    int idx = blockIdx.x * 256 + threadIdx.x;   // 0 .. 524287
    int kg = idx & 7;
    int r  = (idx >> 3) & 31;
    int c  = (idx >> 8) & 15;
    int j  = idx >> 12;

    int gate = r >> 3;
    int u    = 8 * j + (r & 7);
    const float* src = Whh + ((size_t)(gate * HH + u)) * HH + c * KC + kg * 8;
    float4 a = *(const float4*)src;
    float4 b = *(const float4*)(src + 4);

    uint32_t h0, l0, h1, l1, h2, l2, h3, l3;
    split2(a.x, a.y, h0, l0);
    split2(a.z, a.w, h1, l1);
    split2(b.x, b.y, h2, l2);
    split2(b.z, b.w, h3, l3);

    size_t off = ((size_t)(j * NCHUNK + c)) * 4096 + (size_t)r * 128 + (size_t)kg * 16;
    *(uint4*)(g_whi2 + off) = make_uint4(h0, h1, h2, h3);
    *(uint4*)(g_wlo2 + off) = make_uint4(l0, l1, l2, l3);
}

// ---------------------------------------------------------------------------
// Init: h0 -> bf16 hi/lo blobs (buffer 0, layout [b][k]), c0 -> g_c.
// ---------------------------------------------------------------------------
__global__ __launch_bounds__(256)
void init_hc2_kernel(const float* __restrict__ h0, const float* __restrict__ c0)
{
    int idx = blockIdx.x * 256 + threadIdx.x;   // 0 .. 8191
    int kg = idx & 127;
    int b  = idx >> 7;
    int k  = kg * 8;

    const float* src = h0 + (size_t)b * HH + k;
    float4 a = *(const float4*)src;
    float4 bb = *(const float4*)(src + 4);

    uint32_t h0_, l0_, h1_, l1_, h2_, l2_, h3_, l3_;
    split2(a.x, a.y, h0_, l0_);
    split2(a.z, a.w, h1_, l1_);
    split2(bb.x, bb.y, h2_, l2_);
    split2(bb.z, bb.w, h3_, l3_);

    size_t off = (size_t)b * (HH * 2) + (size_t)k * 2;
    *(uint4*)(g_hbhi[0] + off) = make_uint4(h0_, h1_, h2_, h3_);
    *(uint4*)(g_hblo[0] + off) = make_uint4(l0_, l1_, l2_, l3_);

    const float* cs = c0 + (size_t)b * HH + k;
    float* cd = g_c + (size_t)b * HH + k;
    *(float4*)cd       = *(const float4*)cs;
    *(float4*)(cd + 4) = *(const float4*)(cs + 4);
}

// ---------------------------------------------------------------------------
// Step kernel (mma.sync bf16x3): 128 CTAs x 256 threads.
// CTA j: G[32 rows = 4 gates x units 8j..8j+8][64 batch] = Wtile * h.
// 4-stage cp.async pipeline over 16 K-chunks of 64; fused LSTM epilogue.
// ---------------------------------------------------------------------------
__device__ __forceinline__ void load_stage(uint32_t smb, int s, int c, int j,
                                           int rbuf, int tid)
{
    uint32_t stg = smb + (uint32_t)s * SSTG;
    int row = tid >> 3;          // 0..31
    int c16 = tid & 7;           // 16B column within 128B row
    uint32_t d_inner = (uint32_t)row * 144 + (uint32_t)c16 * 16;
    uint32_t d_inner2 = (uint32_t)(row + 32) * 144 + (uint32_t)c16 * 16;
    size_t s_inner = (size_t)row * 128 + (size_t)c16 * 16;

    const unsigned char* wh = g_whi2 + ((size_t)(j * NCHUNK + c)) * 4096;
    const unsigned char* wl = g_wlo2 + ((size_t)(j * NCHUNK + c)) * 4096;
    cpasync16(stg + AHI + d_inner, wh + s_inner);
    cpasync16(stg + ALO + d_inner, wl + s_inner);

    const unsigned char* hh = g_hbhi[rbuf] + (size_t)c * 128;   // [b][k] rows of 2048B
    const unsigned char* hl = g_hblo[rbuf] + (size_t)c * 128;
    size_t hs1 = (size_t)row * 2048 + (size_t)c16 * 16;
    size_t hs2 = (size_t)(row + 32) * 2048 + (size_t)c16 * 16;
    cpasync16(stg + BHI + d_inner,  hh + hs1);
    cpasync16(stg + BHI + d_inner2, hh + hs2);
    cpasync16(stg + BLO + d_inner,  hl + hs1);
    cpasync16(stg + BLO + d_inner2, hl + hs2);
}

__global__ __launch_bounds__(256, 1)
void step3_kernel(int t, float* __restrict__ out)
{
    extern __shared__ char sm[];
    uint32_t smb = smem_u32(sm);

    const int tid  = threadIdx.x;
    const int wid  = tid >> 5;
    const int lane = tid & 31;
    const int j    = blockIdx.x;
    const int rbuf = t & 1;
    const int wbuf = rbuf ^ 1;
    const int n0   = j * 8;

    const int warpM = wid & 1;
    const int warpN = wid >> 1;
    const int m0  = warpM * 16;
    const int bn0 = warpN * 16;

    // per-lane ldmatrix source offsets (bytes, within a tile region)
    // A (non-trans): mat0=(m0..7,k0..7) mat1=(m8..15,k0..7) mat2=(m0..7,k8..15) mat3=(m8..15,k8..15)
    const int mat = lane >> 3;
    const uint32_t aoff = (uint32_t)(m0 + (lane & 7) + ((mat & 1) << 3)) * 144
                        + (uint32_t)(mat >> 1) * 16;
    // B (non-trans on [n][k] storage): mat0=(n0..7,k0..7) mat1=(n0..7,k8..15)
    //                                  mat2=(n8..15,k0..7) mat3=(n8..15,k8..15)
    // fragment: lane l -> (n = l/4, k pair = 2*(l%4)) == mma B operand layout.
    const uint32_t boff = (uint32_t)(bn0 + (lane & 7) + ((mat >> 1) << 3)) * 144
                        + (uint32_t)(mat & 1) * 16;

    float acc[2][4];
#pragma unroll
    for (int i = 0; i < 2; i++)
#pragma unroll
        for (int k = 0; k < 4; k++) acc[i][k] = 0.0f;

    // precharge 3 stages
#pragma unroll
    for (int c = 0; c < 3; c++) { load_stage(smb, c, c, j, rbuf, tid); CP_COMMIT(); }

    for (int c = 0; c < NCHUNK; c++) {
        if (c + 3 < NCHUNK) load_stage(smb, (c + 3) & 3, c + 3, j, rbuf, tid);
        CP_COMMIT();
        CP_WAIT3();
        __syncthreads();

        const uint32_t stg = smb + (uint32_t)(c & 3) * SSTG;
#pragma unroll
        for (int ks = 0; ks < 4; ks++) {
            const uint32_t kb = (uint32_t)ks * 32;
            uint32_t ah[4], al[4], bh[4], bl[4];
            ldm4(ah, stg + AHI + aoff + kb);
            ldm4(al, stg + ALO + aoff + kb);
            ldm4(bh, stg + BHI + boff + kb);
            ldm4(bl, stg + BLO + boff + kb);
            mma16816(acc[0], ah, bh[0], bh[1]);
            mma16816(acc[1], ah, bh[2], bh[3]);
            mma16816(acc[0], ah, bl[0], bl[1]);
            mma16816(acc[1], ah, bl[2], bl[3]);
            mma16816(acc[0], al, bh[0], bh[1]);
            mma16816(acc[1], al, bh[2], bh[3]);
        }
        __syncthreads();
    }

    // ---- gate exchange: fragments -> smem Gs[32][68] (overlays stage 0) ----
    float* gs = (float*)sm;
    {
        const int g0  = lane >> 2;
        const int tig = lane & 3;
        const int row0 = m0 + g0;
        const int col0 = bn0 + tig * 2;
        gs[row0 * 68 + col0]           = acc[0][0];
        gs[row0 * 68 + col0 + 1]       = acc[0][1];
        gs[(row0 + 8) * 68 + col0]     = acc[0][2];
        gs[(row0 + 8) * 68 + col0 + 1] = acc[0][3];
        gs[row0 * 68 + col0 + 8]       = acc[1][0];
        gs[row0 * 68 + col0 + 9]       = acc[1][1];
        gs[(row0 + 8) * 68 + col0 + 8] = acc[1][2];
        gs[(row0 + 8) * 68 + col0 + 9] = acc[1][3];
    }
    __syncthreads();

    // ---- fused LSTM epilogue: thread b handles 8 units ----
    if (tid < BB) {
        const int b = tid;
        const float* xp = g_xproj + ((size_t)t * BB + b) * G4 + n0;
        float xi[8], xf[8], xg[8], xo[8], cc[8], hv[8];
        *(float4*)&xi[0] = *(const float4*)(xp);
        *(float4*)&xi[4] = *(const float4*)(xp + 4);
        *(float4*)&xf[0] = *(const float4*)(xp + HH);
        *(float4*)&xf[4] = *(const float4*)(xp + HH + 4);
        *(float4*)&xg[0] = *(const float4*)(xp + 2 * HH);
        *(float4*)&xg[4] = *(const float4*)(xp + 2 * HH + 4);
        *(float4*)&xo[0] = *(const float4*)(xp + 3 * HH);
        *(float4*)&xo[4] = *(const float4*)(xp + 3 * HH + 4);

        float* cp = g_c + (size_t)b * HH + n0;
        *(float4*)&cc[0] = *(const float4*)(cp);
        *(float4*)&cc[4] = *(const float4*)(cp + 4);

#pragma unroll
        for (int u = 0; u < 8; u++) {
            float gi = gs[(u)      * 68 + b] + xi[u];
            float gf = gs[(8 + u)  * 68 + b] + xf[u];
            float gg = gs[(16 + u) * 68 + b] + xg[u];
            float go = gs[(24 + u) * 68 + b] + xo[u];
            float ii = 1.0f / (1.0f + expf(-gi));
            float ff = 1.0f / (1.0f + expf(-gf));
            float gt = tanhf(gg);
            float oo = 1.0f / (1.0f + expf(-go));
            float cn = ff * cc[u] + ii * gt;
            cc[u] = cn;
            hv[u] = oo * tanhf(cn);
        }

        *(float4*)(cp)     = *(float4*)&cc[0];
        *(float4*)(cp + 4) = *(float4*)&cc[4];

        float* op = out + ((size_t)t * BB + b) * HH + n0;
        *(float4*)(op)     = *(float4*)&hv[0];
        *(float4*)(op + 4) = *(float4*)&hv[4];

        // bf16 hi/lo h blobs for next step
        uint32_t h0_, l0_, h1_, l1_, h2_, l2_, h3_, l3_;
        split2(hv[0], hv[1], h0_, l0_);
        split2(hv[2], hv[3], h1_, l1_);
        split2(hv[4], hv[5], h2_, l2_);
        split2(hv[6], hv[7], h3_, l3_);
        size_t off = (size_t)b * (HH * 2) + (size_t)n0 * 2;
        *(uint4*)(g_hbhi[wbuf] + off) = make_uint4(h0_, h1_, h2_, h3_);
        *(uint4*)(g_hblo[wbuf] + off) = make_uint4(l0_, l1_, l2_, l3_);
    }
}

// ---------------------------------------------------------------------------
// Launch
// ---------------------------------------------------------------------------
extern "C" void kernel_launch(void* const* d_in, const int* in_sizes, int n_in,
                              void* d_out, int out_size)
{
    const float* xs  = (const float*)d_in[0];   // [T,B,IN]
    const float* h0  = (const float*)d_in[1];   // [B,H]
    const float* c0  = (const float*)d_in[2];   // [B,H]
    const float* Wih = (const float*)d_in[3];   // [4H,IN]
    const float* Whh = (const float*)d_in[4];   // [4H,H]
    const float* bih = (const float*)d_in[5];   // [4H]
    const float* bhh = (const float*)d_in[6];   // [4H]
    float* out = (float*)d_out;                 // [T,B,H]

    (void)in_sizes; (void)n_in; (void)out_size;

    cudaFuncSetAttribute(step3_kernel, cudaFuncAttributeMaxDynamicSharedMemorySize, SMEM_REQ);

    dim3 grid1(G4 / 128, (TT * BB) / 128);      // 32 x 256
    xproj_kernel<<<grid1, 256>>>(xs, Wih, bih, bhh);
    prep_w2_kernel<<<2048, 256>>>(Whh);
    init_hc2_kernel<<<32, 256>>>(h0, c0);

    for (int t = 0; t < TT; t++) {
        step3_kernel<<<NCTA2, 256, SMEM_REQ>>>(t, out);
    }
}

// round 5
// speedup vs baseline: 2.7372x; 1.2113x over previous
#include <cuda_runtime.h>
#include <cuda_bf16.h>
#include <stdint.h>
#include <math.h>

// Problem constants
#define TT   512
#define BB   64
#define INN  512
#define HH   1024
#define G4   4096   // 4*HH

#define NCTAP  128     // persistent CTAs; CTA j owns units [8j, 8j+8), all 4 gates => M=32 rows
#define NCHUNK 16      // K chunks of 64

// ---------------- persistent-kernel smem layout (bytes) ----------------
// W rows: 1024 k * 2B = 2048B payload, pitch 2064 (16B rotation -> conflict-free ldmatrix)
#define WPITCH 2064
#define SM_W_HI 0
#define SM_W_LO 66048                    // 32*2064
// h stages: 4 stages x 2 versions(hi/lo); 64 rows x 128B payload, pitch 144
#define SM_H    132096
#define HVER    9216                     // 64*144
#define HSTG    18432                    // 2 versions
#define SM_XP   205824                   // 132096 + 4*18432
#define SMEM_REQ 214016                  // + 8192 xproj tile

// ---------------- device scratch (allocation-free rule) ----------------
__device__ float g_xproj[(size_t)TT * BB * G4];                     // [T*B][4H]
__device__ __align__(16) unsigned char g_whi3[(size_t)NCTAP * 32 * HH * 2];  // 8 MB
__device__ __align__(16) unsigned char g_wlo3[(size_t)NCTAP * 32 * HH * 2];  // 8 MB
__device__ __align__(16) unsigned char g_hbhi[BB * HH * 2];         // h hi bf16 [b][k]
__device__ __align__(16) unsigned char g_hblo[BB * HH * 2];         // h lo bf16 [b][k]
__device__ unsigned g_cnt;                                          // barrier arrivals
__device__ volatile unsigned g_epoch;                               // barrier epoch

// ---------------- helpers ----------------
__device__ __forceinline__ uint32_t smem_u32(const void* p) {
    uint32_t a;
    asm("{ .reg .u64 t; cvta.to.shared.u64 t, %1; cvt.u32.u64 %0, t; }" : "=r"(a) : "l"(p));
    return a;
}

__device__ __forceinline__ void split2(float a, float b, uint32_t& hi, uint32_t& lo) {
    __nv_bfloat16 ah = __float2bfloat16(a), bh = __float2bfloat16(b);
    float ar = a - __bfloat162float(ah);
    float br = b - __bfloat162float(bh);
    __nv_bfloat16 al = __float2bfloat16(ar), bl = __float2bfloat16(br);
    hi = (uint32_t)__bfloat16_as_ushort(ah) | ((uint32_t)__bfloat16_as_ushort(bh) << 16);
    lo = (uint32_t)__bfloat16_as_ushort(al) | ((uint32_t)__bfloat16_as_ushort(bl) << 16);
}

// ---------------- PTX wrappers (baseline compute_103 features only) ----------------
__device__ __forceinline__ void cpasync16(uint32_t dst, const void* src) {
    asm volatile("cp.async.cg.shared.global [%0], [%1], 16;" :: "r"(dst), "l"(src) : "memory");
}
#define CP_COMMIT() asm volatile("cp.async.commit_group;" ::: "memory")
#define CP_WAIT2()  asm volatile("cp.async.wait_group 2;" ::: "memory")
#define CP_WAIT0()  asm volatile("cp.async.wait_group 0;" ::: "memory")

__device__ __forceinline__ void ldm4(uint32_t* r, uint32_t addr) {
    asm volatile("ldmatrix.sync.aligned.m8n8.x4.shared.b16 {%0,%1,%2,%3}, [%4];"
        : "=r"(r[0]), "=r"(r[1]), "=r"(r[2]), "=r"(r[3]) : "r"(addr));
}
__device__ __forceinline__ void mma16816(float* d, const uint32_t* a, uint32_t b0, uint32_t b1) {
    asm volatile(
        "mma.sync.aligned.m16n8k16.row.col.f32.bf16.bf16.f32 "
        "{%0,%1,%2,%3}, {%4,%5,%6,%7}, {%8,%9}, {%0,%1,%2,%3};"
        : "+f"(d[0]), "+f"(d[1]), "+f"(d[2]), "+f"(d[3])
        : "r"(a[0]), "r"(a[1]), "r"(a[2]), "r"(a[3]), "r"(b0), "r"(b1));
}

// ---------------------------------------------------------------------------
// x projection GEMM (fp32 SIMT — proven).
// ---------------------------------------------------------------------------
__global__ __launch_bounds__(256, 2)
void xproj_kernel(const float* __restrict__ xs,
                  const float* __restrict__ Wih,
                  const float* __restrict__ bih,
                  const float* __restrict__ bhh)
{
    const int BM = 128, BN = 128, BK = 16;
    __shared__ float As[BK][BM];
    __shared__ float Bs[BK][BN];

    const int tid = threadIdx.x;
    const int tx  = tid & 15;
    const int ty  = tid >> 4;
    const int rm  = blockIdx.y;
    const int cn  = blockIdx.x;

    const float* Ab = xs  + (size_t)rm * BM * INN;
    const float* Bb = Wih + (size_t)cn * BN * INN;

    float acc[8][8];
#pragma unroll
    for (int i = 0; i < 8; i++)
#pragma unroll
        for (int j = 0; j < 8; j++) acc[i][j] = 0.0f;

    const int lr = tid >> 2;
    const int lc = (tid & 3) * 4;

    for (int k0 = 0; k0 < INN; k0 += BK) {
#pragma unroll
        for (int rr = 0; rr < 2; rr++) {
            const int row = lr + rr * 64;
            float4 va = *(const float4*)(Ab + (size_t)row * INN + k0 + lc);
            As[lc + 0][row] = va.x; As[lc + 1][row] = va.y;
            As[lc + 2][row] = va.z; As[lc + 3][row] = va.w;
            float4 vb = *(const float4*)(Bb + (size_t)row * INN + k0 + lc);
            Bs[lc + 0][row] = vb.x; Bs[lc + 1][row] = vb.y;
            Bs[lc + 2][row] = vb.z; Bs[lc + 3][row] = vb.w;
        }
        __syncthreads();

#pragma unroll
        for (int k = 0; k < BK; k++) {
            float ra[8], rb[8];
            *(float4*)(ra)     = *(const float4*)&As[k][ty * 8];
            *(float4*)(ra + 4) = *(const float4*)&As[k][ty * 8 + 4];
            *(float4*)(rb)     = *(const float4*)&Bs[k][tx * 8];
            *(float4*)(rb + 4) = *(const float4*)&Bs[k][tx * 8 + 4];
#pragma unroll
            for (int i = 0; i < 8; i++)
#pragma unroll
                for (int j = 0; j < 8; j++)
                    acc[i][j] += ra[i] * rb[j];
        }
        __syncthreads();
    }

    const int ncol0 = cn * BN + tx * 8;
    float bv[8];
#pragma unroll
    for (int j = 0; j < 8; j++) bv[j] = bih[ncol0 + j] + bhh[ncol0 + j];

#pragma unroll
    for (int i = 0; i < 8; i++) {
        const size_t row = (size_t)rm * BM + ty * 8 + i;
        float* outp = g_xproj + row * G4 + ncol0;
        float4 o0, o1;
        o0.x = acc[i][0] + bv[0]; o0.y = acc[i][1] + bv[1];
        o0.z = acc[i][2] + bv[2]; o0.w = acc[i][3] + bv[3];
        o1.x = acc[i][4] + bv[4]; o1.y = acc[i][5] + bv[5];
        o1.z = acc[i][6] + bv[6]; o1.w = acc[i][7] + bv[7];
        *(float4*)(outp)     = o0;
        *(float4*)(outp + 4) = o1;
    }
}

// ---------------------------------------------------------------------------
// Prep: W_hh -> bf16 hi/lo, contiguous per-CTA tiles [j][r=0..31][k=0..1023].
// Row r: gate = r>>3, unit = 8j + (r&7).
// ---------------------------------------------------------------------------
__global__ __launch_bounds__(256)
void prep_w3_kernel(const float* __restrict__ Whh)
{
    int idx = blockIdx.x * 256 + threadIdx.x;   // 0 .. 524287
    int kg = idx & 127;           // k-group of 8
    int r  = (idx >> 7) & 31;
    int j  = idx >> 12;

    int gate = r >> 3;
    int u    = 8 * j + (r & 7);
    const float* src = Whh + ((size_t)(gate * HH + u)) * HH + kg * 8;
    float4 a = *(const float4*)src;
    float4 b = *(const float4*)(src + 4);

    uint32_t h0, l0, h1, l1, h2, l2, h3, l3;
    split2(a.x, a.y, h0, l0);
    split2(a.z, a.w, h1, l1);
    split2(b.x, b.y, h2, l2);
    split2(b.z, b.w, h3, l3);

    size_t off = ((size_t)(j * 32 + r) * HH + (size_t)kg * 8) * 2;
    *(uint4*)(g_whi3 + off) = make_uint4(h0, h1, h2, h3);
    *(uint4*)(g_wlo3 + off) = make_uint4(l0, l1, l2, l3);
}

// ---------------------------------------------------------------------------
// Init: h0 -> bf16 hi/lo blobs [b][k].
// ---------------------------------------------------------------------------
__global__ __launch_bounds__(256)
void init_h_kernel(const float* __restrict__ h0)
{
    int idx = blockIdx.x * 256 + threadIdx.x;   // 0 .. 8191
    int kg = idx & 127;
    int b  = idx >> 7;
    int k  = kg * 8;

    const float* src = h0 + (size_t)b * HH + k;
    float4 a = *(const float4*)src;
    float4 bb = *(const float4*)(src + 4);

    uint32_t h0_, l0_, h1_, l1_, h2_, l2_, h3_, l3_;
    split2(a.x, a.y, h0_, l0_);
    split2(a.z, a.w, h1_, l1_);
    split2(bb.x, bb.y, h2_, l2_);
    split2(bb.z, bb.w, h3_, l3_);

    size_t off = (size_t)b * (HH * 2) + (size_t)k * 2;
    *(uint4*)(g_hbhi + off) = make_uint4(h0_, h1_, h2_, h3_);
    *(uint4*)(g_hblo + off) = make_uint4(l0_, l1_, l2_, l3_);
}

__global__ void reset_bar_kernel() { g_cnt = 0; g_epoch = 0; }

// ---------------------------------------------------------------------------
// Persistent LSTM kernel: 128 CTAs x 256 threads, one CTA per SM, all resident.
// W tile lives in SMEM for all 512 steps; h streams via 4-stage cp.async;
// cell state in registers; spin grid-barrier between steps.
// ---------------------------------------------------------------------------
__device__ __forceinline__ void load_h_chunk(uint32_t smb, int s, int c, int tid)
{
    uint32_t stg = smb + SM_H + (uint32_t)s * HSTG;
#pragma unroll
    for (int n = 0; n < 2; n++) {
        int i = tid + n * 256;            // 0..511
        int row = i >> 3;                 // batch 0..63
        int col = i & 7;                  // 16B col within 128B
        uint32_t d = (uint32_t)row * 144 + (uint32_t)col * 16;
        size_t sg = (size_t)row * 2048 + (size_t)c * 128 + (size_t)col * 16;
        cpasync16(stg + d,        g_hbhi + sg);
        cpasync16(stg + HVER + d, g_hblo + sg);
    }
}

__global__ __launch_bounds__(256, 1)
void persist_kernel(const float* __restrict__ c0, float* __restrict__ out)
{
    extern __shared__ char sm[];
    uint32_t smb = smem_u32(sm);

    const int tid  = threadIdx.x;
    const int wid  = tid >> 5;
    const int lane = tid & 31;
    const int j    = blockIdx.x;
    const int n0   = j * 8;

    const int warpM = wid & 1;
    const int warpN = wid >> 1;
    const int m0  = warpM * 16;
    const int bn0 = warpN * 16;

    const int mat = lane >> 3;
    // A (W, non-trans ldmatrix on [m][k], pitch 2064)
    const uint32_t a_row = (uint32_t)(m0 + (lane & 7) + ((mat & 1) << 3));
    const uint32_t aW    = a_row * WPITCH + (uint32_t)(mat >> 1) * 16;
    // B (h, non-trans ldmatrix on [n][k], pitch 144)
    const uint32_t boff  = (uint32_t)(bn0 + (lane & 7) + ((mat >> 1) << 3)) * 144
                         + (uint32_t)(mat & 1) * 16;

    // ---- load W tile into persistent SMEM (once) ----
    {
        const unsigned char* wh = g_whi3 + (size_t)j * 65536;
        const unsigned char* wl = g_wlo3 + (size_t)j * 65536;
#pragma unroll
        for (int n = 0; n < 16; n++) {
            int e = n * 256 + tid;            // 0..4095 (16B units)
            uint32_t d = (uint32_t)(e >> 7) * WPITCH + (uint32_t)(e & 127) * 16;
            cpasync16(smb + SM_W_HI + d, wh + (size_t)e * 16);
            cpasync16(smb + SM_W_LO + d, wl + (size_t)e * 16);
        }
        CP_COMMIT();
        CP_WAIT0();
    }

    // ---- cell state in registers: thread owns (b = tid>>2, units up..up+1) ----
    const int eb = tid >> 2;
    const int eup = (tid & 3) * 2;
    float2 creg = *(const float2*)(c0 + (size_t)eb * HH + n0 + eup);
    __syncthreads();

    float* gs = (float*)(sm + SM_H);          // gate exchange overlay (after drain)
    const float* xpb = (const float*)(sm + SM_XP);

    for (int t = 0; t < TT; t++) {
        // ---- prologue: chunks 0..2 (+ xproj tile folded into group 0) ----
        load_h_chunk(smb, 0, 0, tid);
        {
            // xproj tile: 64 b x 4 gates x 8 floats -> smem [b][g][8]
#pragma unroll
            for (int n = 0; n < 2; n++) {
                int i = tid * 2 + n;              // 0..511
                int half = i & 1;
                int g = (i >> 1) & 3;
                int b = i >> 3;
                const float* src = g_xproj + ((size_t)t * BB + b) * G4
                                 + (size_t)g * HH + n0 + half * 4;
                cpasync16(smb + SM_XP + (uint32_t)b * 128 + (uint32_t)g * 32
                          + (uint32_t)half * 16, src);
            }
        }
        CP_COMMIT();
        load_h_chunk(smb, 1, 1, tid);
        CP_COMMIT();
        load_h_chunk(smb, 2, 2, tid);
        CP_COMMIT();

        float acc[2][4];
#pragma unroll
        for (int i = 0; i < 2; i++)
#pragma unroll
            for (int k = 0; k < 4; k++) acc[i][k] = 0.0f;

        // ---- 16 K-chunks, 4-stage pipeline, 1 syncthreads per chunk ----
        for (int c = 0; c < NCHUNK; c++) {
            CP_WAIT2();
            __syncthreads();
            if (c + 3 < NCHUNK) load_h_chunk(smb, (c + 3) & 3, c + 3, tid);
            CP_COMMIT();

            const uint32_t stg = smb + SM_H + (uint32_t)(c & 3) * HSTG;
            const uint32_t wcol = (uint32_t)c * 128;
#pragma unroll
            for (int ks = 0; ks < 4; ks++) {
                const uint32_t kb = (uint32_t)ks * 32;
                uint32_t ah[4], al[4], bh[4], bl[4];
                ldm4(ah, smb + SM_W_HI + aW + wcol + kb);
                ldm4(al, smb + SM_W_LO + aW + wcol + kb);
                ldm4(bh, stg + boff + kb);
                ldm4(bl, stg + HVER + boff + kb);
                mma16816(acc[0], ah, bh[0], bh[1]);
                mma16816(acc[1], ah, bh[2], bh[3]);
                mma16816(acc[0], ah, bl[0], bl[1]);
                mma16816(acc[1], ah, bl[2], bl[3]);
                mma16816(acc[0], al, bh[0], bh[1]);
                mma16816(acc[1], al, bh[2], bh[3]);
            }
        }
        __syncthreads();

        // ---- gate exchange: fragments -> gs[32][68] ----
        {
            const int g0  = lane >> 2;
            const int tig = lane & 3;
            const int row0 = m0 + g0;
            const int col0 = bn0 + tig * 2;
            gs[row0 * 68 + col0]           = acc[0][0];
            gs[row0 * 68 + col0 + 1]       = acc[0][1];
            gs[(row0 + 8) * 68 + col0]     = acc[0][2];
            gs[(row0 + 8) * 68 + col0 + 1] = acc[0][3];
            gs[row0 * 68 + col0 + 8]       = acc[1][0];
            gs[row0 * 68 + col0 + 9]       = acc[1][1];
            gs[(row0 + 8) * 68 + col0 + 8] = acc[1][2];
            gs[(row0 + 8) * 68 + col0 + 9] = acc[1][3];
        }
        __syncthreads();

        // ---- fused epilogue: (b, 2 units) per thread; c in registers ----
        {
            float hv0, hv1;
            {
                const int u = eup;
                float gi = gs[(u)      * 68 + eb] + xpb[eb * 32 + 0 * 8 + u];
                float gf = gs[(8 + u)  * 68 + eb] + xpb[eb * 32 + 1 * 8 + u];
                float gg = gs[(16 + u) * 68 + eb] + xpb[eb * 32 + 2 * 8 + u];
                float go = gs[(24 + u) * 68 + eb] + xpb[eb * 32 + 3 * 8 + u];
                float ii = 1.0f / (1.0f + expf(-gi));
                float ff = 1.0f / (1.0f + expf(-gf));
                float gt = tanhf(gg);
                float oo = 1.0f / (1.0f + expf(-go));
                float cn = ff * creg.x + ii * gt;
                creg.x = cn;
                hv0 = oo * tanhf(cn);
            }
            {
                const int u = eup + 1;
                float gi = gs[(u)      * 68 + eb] + xpb[eb * 32 + 0 * 8 + u];
                float gf = gs[(8 + u)  * 68 + eb] + xpb[eb * 32 + 1 * 8 + u];
                float gg = gs[(16 + u) * 68 + eb] + xpb[eb * 32 + 2 * 8 + u];
                float go = gs[(24 + u) * 68 + eb] + xpb[eb * 32 + 3 * 8 + u];
                float ii = 1.0f / (1.0f + expf(-gi));
                float ff = 1.0f / (1.0f + expf(-gf));
                float gt = tanhf(gg);
                float oo = 1.0f / (1.0f + expf(-go));
                float cn = ff * creg.y + ii * gt;
                creg.y = cn;
                hv1 = oo * tanhf(cn);
            }

            float2 hv = make_float2(hv0, hv1);
            *(float2*)(out + ((size_t)t * BB + eb) * HH + n0 + eup) = hv;

            uint32_t hi, lo;
            split2(hv0, hv1, hi, lo);
            size_t hoff = (size_t)eb * 2048 + (size_t)(n0 + eup) * 2;
            *(uint32_t*)(g_hbhi + hoff) = hi;
            *(uint32_t*)(g_hblo + hoff) = lo;
        }
        __syncthreads();

        // ---- grid barrier (h blobs for step t visible before step t+1 loads) ----
        if (tid == 0) {
            __threadfence();
            unsigned arrived = atomicAdd(&g_cnt, 1u);
            if (arrived == (unsigned)(t * NCTAP + NCTAP - 1)) {
                __threadfence();
                g_epoch = (unsigned)(t + 1);
            } else {
                while (g_epoch < (unsigned)(t + 1)) __nanosleep(64);
            }
            __threadfence();
        }
        __syncthreads();
    }
}

// ---------------------------------------------------------------------------
// Launch
// ---------------------------------------------------------------------------
extern "C" void kernel_launch(void* const* d_in, const int* in_sizes, int n_in,
                              void* d_out, int out_size)
{
    const float* xs  = (const float*)d_in[0];   // [T,B,IN]
    const float* h0  = (const float*)d_in[1];   // [B,H]
    const float* c0  = (const float*)d_in[2];   // [B,H]
    const float* Wih = (const float*)d_in[3];   // [4H,IN]
    const float* Whh = (const float*)d_in[4];   // [4H,H]
    const float* bih = (const float*)d_in[5];   // [4H]
    const float* bhh = (const float*)d_in[6];   // [4H]
    float* out = (float*)d_out;                 // [T,B,H]

    (void)in_sizes; (void)n_in; (void)out_size;

    cudaFuncSetAttribute(persist_kernel, cudaFuncAttributeMaxDynamicSharedMemorySize, SMEM_REQ);

    dim3 grid1(G4 / 128, (TT * BB) / 128);      // 32 x 256
    xproj_kernel<<<grid1, 256>>>(xs, Wih, bih, bhh);
    prep_w3_kernel<<<2048, 256>>>(Whh);
    init_h_kernel<<<32, 256>>>(h0);
    reset_bar_kernel<<<1, 1>>>();

    persist_kernel<<<NCTAP, 256, SMEM_REQ>>>(c0, out);
}

// round 6
// speedup vs baseline: 3.2849x; 1.2001x over previous
#include <cuda_runtime.h>
#include <cuda_bf16.h>
#include <cuda_fp16.h>
#include <stdint.h>
#include <math.h>

// Problem constants
#define TT   512
#define BB   64
#define INN  512
#define HH   1024
#define G4   4096   // 4*HH

#define NCTAP  128     // persistent CTAs; CTA j owns units [8j, 8j+8), all 4 gates => M=32 rows
#define NCHUNK 16      // K chunks of 64
#define LOSCALE 2048.0f
#define INV_LOSCALE (1.0f / 2048.0f)

// ---------------- persistent-kernel smem layout (bytes) ----------------
// W rows: 1024 k * 2B = 2048B payload, pitch 2064 (16B rotation -> conflict-free ldmatrix)
#define WPITCH 2064
#define SM_W_HI 0
#define SM_W_LO 66048                    // 32*2064
// h stages: 4 stages, single fp16 version; 64 rows x 128B payload, pitch 144
#define SM_H    132096
#define HSTG    9216                     // 64*144
#define SM_XP   168960                   // 132096 + 4*9216
#define SMEM_REQ 177152                  // + 8192 xproj tile

// ---------------- device scratch (allocation-free rule) ----------------
__device__ float g_xproj[(size_t)TT * BB * G4];                     // [T*B][4H]
__device__ __align__(16) unsigned char g_whi3[(size_t)NCTAP * 32 * HH * 2];  // 8 MB fp16 hi
__device__ __align__(16) unsigned char g_wlo3[(size_t)NCTAP * 32 * HH * 2];  // 8 MB fp16 lo*2048
__device__ __align__(16) unsigned char g_hb[2][BB * HH * 2];        // h fp16 [b][k], ping-pong
__device__ unsigned g_cnt;                                          // barrier arrivals
__device__ volatile unsigned g_epoch;                               // barrier epoch

// ---------------- helpers ----------------
__device__ __forceinline__ uint32_t smem_u32(const void* p) {
    uint32_t a;
    asm("{ .reg .u64 t; cvta.to.shared.u64 t, %1; cvt.u32.u64 %0, t; }" : "=r"(a) : "l"(p));
    return a;
}

// W split: hi = fp16(w), lo = fp16((w - hi) * 2048)   (residual kept normal-range)
__device__ __forceinline__ void splitw2(float a, float b, uint32_t& hi, uint32_t& lo) {
    __half ah = __float2half_rn(a), bh = __float2half_rn(b);
    float ar = (a - __half2float(ah)) * LOSCALE;
    float br = (b - __half2float(bh)) * LOSCALE;
    __half al = __float2half_rn(ar), bl = __float2half_rn(br);
    hi = (uint32_t)__half_as_ushort(ah) | ((uint32_t)__half_as_ushort(bh) << 16);
    lo = (uint32_t)__half_as_ushort(al) | ((uint32_t)__half_as_ushort(bl) << 16);
}

// ---------------- PTX wrappers (baseline compute_103 features only) ----------------
__device__ __forceinline__ void cpasync16(uint32_t dst, const void* src) {
    asm volatile("cp.async.cg.shared.global [%0], [%1], 16;" :: "r"(dst), "l"(src) : "memory");
}
#define CP_COMMIT() asm volatile("cp.async.commit_group;" ::: "memory")
#define CP_WAIT2()  asm volatile("cp.async.wait_group 2;" ::: "memory")
#define CP_WAIT0()  asm volatile("cp.async.wait_group 0;" ::: "memory")

__device__ __forceinline__ void ldm4(uint32_t* r, uint32_t addr) {
    asm volatile("ldmatrix.sync.aligned.m8n8.x4.shared.b16 {%0,%1,%2,%3}, [%4];"
        : "=r"(r[0]), "=r"(r[1]), "=r"(r[2]), "=r"(r[3]) : "r"(addr));
}
__device__ __forceinline__ void mma16816h(float* d, const uint32_t* a, uint32_t b0, uint32_t b1) {
    asm volatile(
        "mma.sync.aligned.m16n8k16.row.col.f32.f16.f16.f32 "
        "{%0,%1,%2,%3}, {%4,%5,%6,%7}, {%8,%9}, {%0,%1,%2,%3};"
        : "+f"(d[0]), "+f"(d[1]), "+f"(d[2]), "+f"(d[3])
        : "r"(a[0]), "r"(a[1]), "r"(a[2]), "r"(a[3]), "r"(b0), "r"(b1));
}

// ---------------------------------------------------------------------------
// x projection GEMM (fp32 SIMT — proven).
// ---------------------------------------------------------------------------
__global__ __launch_bounds__(256, 2)
void xproj_kernel(const float* __restrict__ xs,
                  const float* __restrict__ Wih,
                  const float* __restrict__ bih,
                  const float* __restrict__ bhh)
{
    const int BM = 128, BN = 128, BK = 16;
    __shared__ float As[BK][BM];
    __shared__ float Bs[BK][BN];

    const int tid = threadIdx.x;
    const int tx  = tid & 15;
    const int ty  = tid >> 4;
    const int rm  = blockIdx.y;
    const int cn  = blockIdx.x;

    const float* Ab = xs  + (size_t)rm * BM * INN;
    const float* Bb = Wih + (size_t)cn * BN * INN;

    float acc[8][8];
#pragma unroll
    for (int i = 0; i < 8; i++)
#pragma unroll
        for (int j = 0; j < 8; j++) acc[i][j] = 0.0f;

    const int lr = tid >> 2;
    const int lc = (tid & 3) * 4;

    for (int k0 = 0; k0 < INN; k0 += BK) {
#pragma unroll
        for (int rr = 0; rr < 2; rr++) {
            const int row = lr + rr * 64;
            float4 va = *(const float4*)(Ab + (size_t)row * INN + k0 + lc);
            As[lc + 0][row] = va.x; As[lc + 1][row] = va.y;
            As[lc + 2][row] = va.z; As[lc + 3][row] = va.w;
            float4 vb = *(const float4*)(Bb + (size_t)row * INN + k0 + lc);
            Bs[lc + 0][row] = vb.x; Bs[lc + 1][row] = vb.y;
            Bs[lc + 2][row] = vb.z; Bs[lc + 3][row] = vb.w;
        }
        __syncthreads();

#pragma unroll
        for (int k = 0; k < BK; k++) {
            float ra[8], rb[8];
            *(float4*)(ra)     = *(const float4*)&As[k][ty * 8];
            *(float4*)(ra + 4) = *(const float4*)&As[k][ty * 8 + 4];
            *(float4*)(rb)     = *(const float4*)&Bs[k][tx * 8];
            *(float4*)(rb + 4) = *(const float4*)&Bs[k][tx * 8 + 4];
#pragma unroll
            for (int i = 0; i < 8; i++)
#pragma unroll
                for (int j = 0; j < 8; j++)
                    acc[i][j] += ra[i] * rb[j];
        }
        __syncthreads();
    }

    const int ncol0 = cn * BN + tx * 8;
    float bv[8];
#pragma unroll
    for (int j = 0; j < 8; j++) bv[j] = bih[ncol0 + j] + bhh[ncol0 + j];

#pragma unroll
    for (int i = 0; i < 8; i++) {
        const size_t row = (size_t)rm * BM + ty * 8 + i;
        float* outp = g_xproj + row * G4 + ncol0;
        float4 o0, o1;
        o0.x = acc[i][0] + bv[0]; o0.y = acc[i][1] + bv[1];
        o0.z = acc[i][2] + bv[2]; o0.w = acc[i][3] + bv[3];
        o1.x = acc[i][4] + bv[4]; o1.y = acc[i][5] + bv[5];
        o1.z = acc[i][6] + bv[6]; o1.w = acc[i][7] + bv[7];
        *(float4*)(outp)     = o0;
        *(float4*)(outp + 4) = o1;
    }
}

// ---------------------------------------------------------------------------
// Prep: W_hh -> fp16 hi + fp16 lo(*2048), per-CTA tiles [j][r=0..31][k=0..1023].
// Row r: gate = r>>3, unit = 8j + (r&7).
// ---------------------------------------------------------------------------
__global__ __launch_bounds__(256)
void prep_w3_kernel(const float* __restrict__ Whh)
{
    int idx = blockIdx.x * 256 + threadIdx.x;   // 0 .. 524287
    int kg = idx & 127;           // k-group of 8
    int r  = (idx >> 7) & 31;
    int j  = idx >> 12;

    int gate = r >> 3;
    int u    = 8 * j + (r & 7);
    const float* src = Whh + ((size_t)(gate * HH + u)) * HH + kg * 8;
    float4 a = *(const float4*)src;
    float4 b = *(const float4*)(src + 4);

    uint32_t h0, l0, h1, l1, h2, l2, h3, l3;
    splitw2(a.x, a.y, h0, l0);
    splitw2(a.z, a.w, h1, l1);
    splitw2(b.x, b.y, h2, l2);
    splitw2(b.z, b.w, h3, l3);

    size_t off = ((size_t)(j * 32 + r) * HH + (size_t)kg * 8) * 2;
    *(uint4*)(g_whi3 + off) = make_uint4(h0, h1, h2, h3);
    *(uint4*)(g_wlo3 + off) = make_uint4(l0, l1, l2, l3);
}

// ---------------------------------------------------------------------------
// Init: h0 -> fp16 blob [b][k], buffer 0.
// ---------------------------------------------------------------------------
__global__ __launch_bounds__(256)
void init_h_kernel(const float* __restrict__ h0)
{
    int idx = blockIdx.x * 256 + threadIdx.x;   // 0 .. 8191
    int kg = idx & 127;
    int b  = idx >> 7;
    int k  = kg * 8;

    const float* src = h0 + (size_t)b * HH + k;
    float4 a = *(const float4*)src;
    float4 bb = *(const float4*)(src + 4);

    __half2 p0 = __floats2half2_rn(a.x, a.y);
    __half2 p1 = __floats2half2_rn(a.z, a.w);
    __half2 p2 = __floats2half2_rn(bb.x, bb.y);
    __half2 p3 = __floats2half2_rn(bb.z, bb.w);

    size_t off = (size_t)b * (HH * 2) + (size_t)k * 2;
    *(uint4*)(g_hb[0] + off) = make_uint4(
        *(uint32_t*)&p0, *(uint32_t*)&p1, *(uint32_t*)&p2, *(uint32_t*)&p3);
}

__global__ void reset_bar_kernel() { g_cnt = 0; g_epoch = 0; }

// ---------------------------------------------------------------------------
// Persistent LSTM kernel: 128 CTAs x 256 threads, all co-resident.
// W (fp16 hi/lo) lives in SMEM for all 512 steps; h (single fp16 plane,
// ping-pong in gmem) streams via 4-stage cp.async; cell state in registers;
// spin grid-barrier between steps.
// ---------------------------------------------------------------------------
__device__ __forceinline__ void load_h_chunk(uint32_t smb, int s, int c, int tid,
                                             const unsigned char* hbase)
{
    uint32_t stg = smb + SM_H + (uint32_t)s * HSTG;
#pragma unroll
    for (int n = 0; n < 2; n++) {
        int i = tid + n * 256;            // 0..511 (16B segs)
        int row = i >> 3;                 // batch 0..63
        int col = i & 7;                  // 16B col within 128B
        uint32_t d = (uint32_t)row * 144 + (uint32_t)col * 16;
        size_t sg = (size_t)row * 2048 + (size_t)c * 128 + (size_t)col * 16;
        cpasync16(stg + d, hbase + sg);
    }
}

__global__ __launch_bounds__(256, 1)
void persist_kernel(const float* __restrict__ c0, float* __restrict__ out)
{
    extern __shared__ char sm[];
    uint32_t smb = smem_u32(sm);

    const int tid  = threadIdx.x;
    const int wid  = tid >> 5;
    const int lane = tid & 31;
    const int j    = blockIdx.x;
    const int n0   = j * 8;

    const int warpM = wid & 1;
    const int warpN = wid >> 1;
    const int m0  = warpM * 16;
    const int bn0 = warpN * 16;

    const int mat = lane >> 3;
    // A (W, non-trans ldmatrix on [m][k], pitch 2064)
    const uint32_t a_row = (uint32_t)(m0 + (lane & 7) + ((mat & 1) << 3));
    const uint32_t aW    = a_row * WPITCH + (uint32_t)(mat >> 1) * 16;
    // B (h, non-trans ldmatrix on [n][k], pitch 144)
    const uint32_t boff  = (uint32_t)(bn0 + (lane & 7) + ((mat >> 1) << 3)) * 144
                         + (uint32_t)(mat & 1) * 16;

    // ---- load W tile into persistent SMEM (once) ----
    {
        const unsigned char* wh = g_whi3 + (size_t)j * 65536;
        const unsigned char* wl = g_wlo3 + (size_t)j * 65536;
#pragma unroll
        for (int n = 0; n < 16; n++) {
            int e = n * 256 + tid;            // 0..4095 (16B units)
            uint32_t d = (uint32_t)(e >> 7) * WPITCH + (uint32_t)(e & 127) * 16;
            cpasync16(smb + SM_W_HI + d, wh + (size_t)e * 16);
            cpasync16(smb + SM_W_LO + d, wl + (size_t)e * 16);
        }
        CP_COMMIT();
        CP_WAIT0();
    }

    // ---- cell state in registers: thread owns (b = tid>>2, units eup..eup+1) ----
    const int eb = tid >> 2;
    const int eup = (tid & 3) * 2;
    float2 creg = *(const float2*)(c0 + (size_t)eb * HH + n0 + eup);
    __syncthreads();

    float* gs = (float*)(sm + SM_H);          // gate exchange overlay (after drain)
    const float* xpb = (const float*)(sm + SM_XP);

    for (int t = 0; t < TT; t++) {
        const unsigned char* hread = g_hb[t & 1];
        unsigned char* hwrite      = g_hb[(t & 1) ^ 1];

        // ---- prologue: chunks 0..2 (+ xproj tile folded into group 0) ----
        load_h_chunk(smb, 0, 0, tid, hread);
        {
            // xproj tile: 64 b x 4 gates x 8 floats -> smem [b][g][8]
#pragma unroll
            for (int n = 0; n < 2; n++) {
                int i = tid * 2 + n;              // 0..511
                int half = i & 1;
                int g = (i >> 1) & 3;
                int b = i >> 3;
                const float* src = g_xproj + ((size_t)t * BB + b) * G4
                                 + (size_t)g * HH + n0 + half * 4;
                cpasync16(smb + SM_XP + (uint32_t)b * 128 + (uint32_t)g * 32
                          + (uint32_t)half * 16, src);
            }
        }
        CP_COMMIT();
        load_h_chunk(smb, 1, 1, tid, hread);
        CP_COMMIT();
        load_h_chunk(smb, 2, 2, tid, hread);
        CP_COMMIT();

        float acc[2][4], acl[2][4];
#pragma unroll
        for (int i = 0; i < 2; i++)
#pragma unroll
            for (int k = 0; k < 4; k++) { acc[i][k] = 0.0f; acl[i][k] = 0.0f; }

        // ---- 16 K-chunks, 4-stage pipeline ----
        for (int c = 0; c < NCHUNK; c++) {
            CP_WAIT2();
            __syncthreads();
            if (c + 3 < NCHUNK) load_h_chunk(smb, (c + 3) & 3, c + 3, tid, hread);
            CP_COMMIT();

            const uint32_t stg = smb + SM_H + (uint32_t)(c & 3) * HSTG;
            const uint32_t wcol = (uint32_t)c * 128;
#pragma unroll
            for (int ks = 0; ks < 4; ks++) {
                const uint32_t kb = (uint32_t)ks * 32;
                uint32_t ah[4], al[4], bh[4];
                ldm4(ah, smb + SM_W_HI + aW + wcol + kb);
                ldm4(al, smb + SM_W_LO + aW + wcol + kb);
                ldm4(bh, stg + boff + kb);
                mma16816h(acc[0], ah, bh[0], bh[1]);
                mma16816h(acc[1], ah, bh[2], bh[3]);
                mma16816h(acl[0], al, bh[0], bh[1]);
                mma16816h(acl[1], al, bh[2], bh[3]);
            }
        }
        __syncthreads();

        // ---- gate exchange: combined fragments -> gs[32][68] ----
        {
            const int g0  = lane >> 2;
            const int tig = lane & 3;
            const int row0 = m0 + g0;
            const int col0 = bn0 + tig * 2;
            gs[row0 * 68 + col0]           = fmaf(acl[0][0], INV_LOSCALE, acc[0][0]);
            gs[row0 * 68 + col0 + 1]       = fmaf(acl[0][1], INV_LOSCALE, acc[0][1]);
            gs[(row0 + 8) * 68 + col0]     = fmaf(acl[0][2], INV_LOSCALE, acc[0][2]);
            gs[(row0 + 8) * 68 + col0 + 1] = fmaf(acl[0][3], INV_LOSCALE, acc[0][3]);
            gs[row0 * 68 + col0 + 8]       = fmaf(acl[1][0], INV_LOSCALE, acc[1][0]);
            gs[row0 * 68 + col0 + 9]       = fmaf(acl[1][1], INV_LOSCALE, acc[1][1]);
            gs[(row0 + 8) * 68 + col0 + 8] = fmaf(acl[1][2], INV_LOSCALE, acc[1][2]);
            gs[(row0 + 8) * 68 + col0 + 9] = fmaf(acl[1][3], INV_LOSCALE, acc[1][3]);
        }
        __syncthreads();

        // ---- fused epilogue: (b, 2 units) per thread; c in registers ----
        {
            float hv0, hv1;
            {
                const int u = eup;
                float gi = gs[(u)      * 68 + eb] + xpb[eb * 32 + 0 * 8 + u];
                float gf = gs[(8 + u)  * 68 + eb] + xpb[eb * 32 + 1 * 8 + u];
                float gg = gs[(16 + u) * 68 + eb] + xpb[eb * 32 + 2 * 8 + u];
                float go = gs[(24 + u) * 68 + eb] + xpb[eb * 32 + 3 * 8 + u];
                float ii = 1.0f / (1.0f + expf(-gi));
                float ff = 1.0f / (1.0f + expf(-gf));
                float gt = tanhf(gg);
                float oo = 1.0f / (1.0f + expf(-go));
                float cn = ff * creg.x + ii * gt;
                creg.x = cn;
                hv0 = oo * tanhf(cn);
            }
            {
                const int u = eup + 1;
                float gi = gs[(u)      * 68 + eb] + xpb[eb * 32 + 0 * 8 + u];
                float gf = gs[(8 + u)  * 68 + eb] + xpb[eb * 32 + 1 * 8 + u];
                float gg = gs[(16 + u) * 68 + eb] + xpb[eb * 32 + 2 * 8 + u];
                float go = gs[(24 + u) * 68 + eb] + xpb[eb * 32 + 3 * 8 + u];
                float ii = 1.0f / (1.0f + expf(-gi));
                float ff = 1.0f / (1.0f + expf(-gf));
                float gt = tanhf(gg);
                float oo = 1.0f / (1.0f + expf(-go));
                float cn = ff * creg.y + ii * gt;
                creg.y = cn;
                hv1 = oo * tanhf(cn);
            }

            *(float2*)(out + ((size_t)t * BB + eb) * HH + n0 + eup) = make_float2(hv0, hv1);

            __half2 hp = __floats2half2_rn(hv0, hv1);
            *(uint32_t*)(hwrite + (size_t)eb * 2048 + (size_t)(n0 + eup) * 2)
                = *(uint32_t*)&hp;
        }
        __syncthreads();

        // ---- grid barrier (h blob for step t+1 visible before it is read) ----
        if (tid == 0) {
            __threadfence();
            unsigned arrived = atomicAdd(&g_cnt, 1u);
            if (arrived == (unsigned)(t * NCTAP + NCTAP - 1)) {
                __threadfence();
                g_epoch = (unsigned)(t + 1);
            } else {
                while (g_epoch < (unsigned)(t + 1)) __nanosleep(32);
            }
            __threadfence();
        }
        __syncthreads();
    }
}

// ---------------------------------------------------------------------------
// Launch
// ---------------------------------------------------------------------------
extern "C" void kernel_launch(void* const* d_in, const int* in_sizes, int n_in,
                              void* d_out, int out_size)
{
    const float* xs  = (const float*)d_in[0];   // [T,B,IN]
    const float* h0  = (const float*)d_in[1];   // [B,H]
    const float* c0  = (const float*)d_in[2];   // [B,H]
    const float* Wih = (const float*)d_in[3];   // [4H,IN]
    const float* Whh = (const float*)d_in[4];   // [4H,H]
    const float* bih = (const float*)d_in[5];   // [4H]
    const float* bhh = (const float*)d_in[6];   // [4H]
    float* out = (float*)d_out;                 // [T,B,H]

    (void)in_sizes; (void)n_in; (void)out_size;

    cudaFuncSetAttribute(persist_kernel, cudaFuncAttributeMaxDynamicSharedMemorySize, SMEM_REQ);

    dim3 grid1(G4 / 128, (TT * BB) / 128);      // 32 x 256
    xproj_kernel<<<grid1, 256>>>(xs, Wih, bih, bhh);
    prep_w3_kernel<<<2048, 256>>>(Whh);
    init_h_kernel<<<32, 256>>>(h0);
    reset_bar_kernel<<<1, 1>>>();

    persist_kernel<<<NCTAP, 256, SMEM_REQ>>>(c0, out);
}

// round 7
// speedup vs baseline: 5.7861x; 1.7614x over previous
#include <cuda_runtime.h>
#include <cuda_fp16.h>
#include <stdint.h>
#include <math.h>

// Problem constants
#define TT   512
#define BB   64
#define INN  512
#define HH   1024
#define G4   4096   // 4*HH

#define NCTAP  128     // persistent CTAs; CTA j owns units [8j, 8j+8), all 4 gates => M=32 rows
#define NCHUNK 16      // K chunks of 64
#define NSTAGE 6

// ---------------- persistent-kernel smem layout (bytes) ----------------
#define WPITCH 2064                      // 1024 fp16 = 2048B payload + 16B rotation
#define SM_W    0
#define SM_H    66048                    // 32*2064
#define HSTG    9216                     // 64 rows * 144
#define SM_XP   121344                   // 66048 + 6*9216
#define SMEM_REQ 129536                  // + 8192 xproj tile

// ---------------- xproj mma kernel smem ----------------
#define XPA     0
#define XPB     18432                    // 128 rows * 144
#define XPSTG   36864
#define XP_SMEM (4 * XPSTG)              // 147456

// ---------------- device scratch (allocation-free rule) ----------------
__device__ float g_xproj[(size_t)TT * BB * G4];                     // [T*B][4H] fp32
__device__ __align__(16) unsigned char g_xh[(size_t)TT * BB * INN * 2];      // xs fp16 [m][k] 32MB
__device__ __align__(16) unsigned char g_wih[(size_t)G4 * INN * 2];          // W_ih fp16 [n][k] 4MB
__device__ __align__(16) unsigned char g_whh[(size_t)NCTAP * 32 * HH * 2];   // W_hh fp16 tiles 8MB
__device__ __align__(16) unsigned char g_hb[2][BB * HH * 2];        // h fp16 [b][k], ping-pong
__device__ unsigned g_cnt;                                          // barrier arrivals
__device__ volatile unsigned g_epoch;                               // barrier epoch

// ---------------- helpers ----------------
__device__ __forceinline__ uint32_t smem_u32(const void* p) {
    uint32_t a;
    asm("{ .reg .u64 t; cvta.to.shared.u64 t, %1; cvt.u32.u64 %0, t; }" : "=r"(a) : "l"(p));
    return a;
}

__device__ __forceinline__ uint4 pack8h(float4 a, float4 b) {
    __half2 p0 = __floats2half2_rn(a.x, a.y);
    __half2 p1 = __floats2half2_rn(a.z, a.w);
    __half2 p2 = __floats2half2_rn(b.x, b.y);
    __half2 p3 = __floats2half2_rn(b.z, b.w);
    return make_uint4(*(uint32_t*)&p0, *(uint32_t*)&p1, *(uint32_t*)&p2, *(uint32_t*)&p3);
}

// ---------------- PTX wrappers (baseline compute_103 features only) ----------------
__device__ __forceinline__ void cpasync16(uint32_t dst, const void* src) {
    asm volatile("cp.async.cg.shared.global [%0], [%1], 16;" :: "r"(dst), "l"(src) : "memory");
}
#define CP_COMMIT() asm volatile("cp.async.commit_group;" ::: "memory")
#define CP_WAIT4()  asm volatile("cp.async.wait_group 4;" ::: "memory")
#define CP_WAIT2()  asm volatile("cp.async.wait_group 2;" ::: "memory")
#define CP_WAIT0()  asm volatile("cp.async.wait_group 0;" ::: "memory")

__device__ __forceinline__ void ldm4(uint32_t* r, uint32_t addr) {
    asm volatile("ldmatrix.sync.aligned.m8n8.x4.shared.b16 {%0,%1,%2,%3}, [%4];"
        : "=r"(r[0]), "=r"(r[1]), "=r"(r[2]), "=r"(r[3]) : "r"(addr));
}
__device__ __forceinline__ void mma16816h(float* d, const uint32_t* a, uint32_t b0, uint32_t b1) {
    asm volatile(
        "mma.sync.aligned.m16n8k16.row.col.f32.f16.f16.f32 "
        "{%0,%1,%2,%3}, {%4,%5,%6,%7}, {%8,%9}, {%0,%1,%2,%3};"
        : "+f"(d[0]), "+f"(d[1]), "+f"(d[2]), "+f"(d[3])
        : "r"(a[0]), "r"(a[1]), "r"(a[2]), "r"(a[3]), "r"(b0), "r"(b1));
}

// ---------------------------------------------------------------------------
// Prep kernels: fp32 -> fp16 conversions.
// ---------------------------------------------------------------------------
__global__ __launch_bounds__(256)
void prep_xh_kernel(const float* __restrict__ xs)
{
    size_t idx = (size_t)blockIdx.x * 256 + threadIdx.x;   // 0 .. 2,097,151
    const float* s = xs + idx * 8;
    float4 a = *(const float4*)s;
    float4 b = *(const float4*)(s + 4);
    *(uint4*)(g_xh + idx * 16) = pack8h(a, b);
}

__global__ __launch_bounds__(256)
void prep_wih_kernel(const float* __restrict__ Wih)
{
    size_t idx = (size_t)blockIdx.x * 256 + threadIdx.x;   // 0 .. 262,143
    const float* s = Wih + idx * 8;
    float4 a = *(const float4*)s;
    float4 b = *(const float4*)(s + 4);
    *(uint4*)(g_wih + idx * 16) = pack8h(a, b);
}

// W_hh -> fp16, per-CTA tiles [j][r=0..31][k=0..1023]. Row r: gate=r>>3, unit=8j+(r&7).
__global__ __launch_bounds__(256)
void prep_whh_kernel(const float* __restrict__ Whh)
{
    int idx = blockIdx.x * 256 + threadIdx.x;   // 0 .. 524287
    int kg = idx & 127;
    int r  = (idx >> 7) & 31;
    int j  = idx >> 12;

    int gate = r >> 3;
    int u    = 8 * j + (r & 7);
    const float* src = Whh + ((size_t)(gate * HH + u)) * HH + kg * 8;
    float4 a = *(const float4*)src;
    float4 b = *(const float4*)(src + 4);

    size_t off = ((size_t)(j * 32 + r) * HH + (size_t)kg * 8) * 2;
    *(uint4*)(g_whh + off) = pack8h(a, b);
}

__global__ __launch_bounds__(256)
void init_h_kernel(const float* __restrict__ h0)
{
    int idx = blockIdx.x * 256 + threadIdx.x;   // 0 .. 8191
    const float* src = h0 + (size_t)idx * 8;
    float4 a = *(const float4*)src;
    float4 b = *(const float4*)(src + 4);
    *(uint4*)(g_hb[0] + (size_t)idx * 16) = pack8h(a, b);
}

__global__ void reset_bar_kernel() { g_cnt = 0; g_epoch = 0; }

// ---------------------------------------------------------------------------
// xproj GEMM on tensor cores (fp16 single plane):
// g_xproj[m][n] = xs[m][k] * Wih[n][k]^T + (bih+bhh)[n],  m=32768, n=4096, k=512.
// CTA tile 128x128, 8 warps (2M x 4N), warp m64 x n32, 8 K-chunks of 64,
// 4-stage cp.async pipeline.
// ---------------------------------------------------------------------------
__device__ __forceinline__ void xp_load_stage(uint32_t smb, int s, int c,
                                              int mbase, int nbase, int tid)
{
    uint32_t stg = smb + (uint32_t)s * XPSTG;
#pragma unroll
    for (int n = 0; n < 4; n++) {
        int i = tid + n * 256;            // 0..1023
        int row = i >> 3;
        int col = i & 7;
        uint32_t d = (uint32_t)row * 144 + (uint32_t)col * 16;
        cpasync16(stg + XPA + d,
                  g_xh + ((size_t)(mbase + row) * INN + (size_t)c * 64 + col * 8) * 2);
        cpasync16(stg + XPB + d,
                  g_wih + ((size_t)(nbase + row) * INN + (size_t)c * 64 + col * 8) * 2);
    }
}

__global__ __launch_bounds__(256, 1)
void xprojmma_kernel(const float* __restrict__ bih, const float* __restrict__ bhh)
{
    extern __shared__ char sm[];
    uint32_t smb = smem_u32(sm);

    const int tid  = threadIdx.x;
    const int wid  = tid >> 5;
    const int lane = tid & 31;
    const int nbase = blockIdx.x * 128;
    const int mbase = blockIdx.y * 128;

    const int m0 = (wid & 1) * 64;
    const int n0 = (wid >> 1) * 32;

    const int mat = lane >> 3;
    const uint32_t arow = (uint32_t)((lane & 7) + ((mat & 1) << 3));
    const uint32_t acol = (uint32_t)(mat >> 1) * 16;
    const uint32_t brow = (uint32_t)((lane & 7) + ((mat >> 1) << 3));
    const uint32_t bcol = (uint32_t)(mat & 1) * 16;

    float acc[4][4][4];
#pragma unroll
    for (int im = 0; im < 4; im++)
#pragma unroll
        for (int in = 0; in < 4; in++)
#pragma unroll
            for (int k = 0; k < 4; k++) acc[im][in][k] = 0.0f;

    // prologue: 3 stages
#pragma unroll
    for (int c = 0; c < 3; c++) { xp_load_stage(smb, c, c, mbase, nbase, tid); CP_COMMIT(); }

    for (int c = 0; c < 8; c++) {
        CP_WAIT2();
        __syncthreads();
        if (c + 3 < 8) xp_load_stage(smb, (c + 3) & 3, c + 3, mbase, nbase, tid);
        CP_COMMIT();

        const uint32_t stg = smb + (uint32_t)(c & 3) * XPSTG;
#pragma unroll
        for (int ks = 0; ks < 4; ks++) {
            const uint32_t kb = (uint32_t)ks * 32;
            uint32_t a[4][4], b0[4], b1[4];
#pragma unroll
            for (int im = 0; im < 4; im++)
                ldm4(a[im], stg + XPA + (uint32_t)(m0 + im * 16 + arow) * 144 + acol + kb);
            ldm4(b0, stg + XPB + (uint32_t)(n0 + brow) * 144 + bcol + kb);
            ldm4(b1, stg + XPB + (uint32_t)(n0 + 16 + brow) * 144 + bcol + kb);
#pragma unroll
            for (int im = 0; im < 4; im++) {
                mma16816h(acc[im][0], a[im], b0[0], b0[1]);
                mma16816h(acc[im][1], a[im], b0[2], b0[3]);
                mma16816h(acc[im][2], a[im], b1[0], b1[1]);
                mma16816h(acc[im][3], a[im], b1[2], b1[3]);
            }
        }
    }

    // epilogue: bias add + direct fp32 stores (float2, coalesced enough)
    const int crow  = lane >> 2;
    const int ccol2 = (lane & 3) * 2;
#pragma unroll
    for (int in = 0; in < 4; in++) {
        const int gcol = nbase + n0 + in * 8 + ccol2;
        float bx = bih[gcol]     + bhh[gcol];
        float by = bih[gcol + 1] + bhh[gcol + 1];
#pragma unroll
        for (int im = 0; im < 4; im++) {
            const int r0 = mbase + m0 + im * 16 + crow;
            float2 v0 = make_float2(acc[im][in][0] + bx, acc[im][in][1] + by);
            float2 v1 = make_float2(acc[im][in][2] + bx, acc[im][in][3] + by);
            *(float2*)(g_xproj + (size_t)r0 * G4 + gcol)       = v0;
            *(float2*)(g_xproj + (size_t)(r0 + 8) * G4 + gcol) = v1;
        }
    }
}

// ---------------------------------------------------------------------------
// Persistent LSTM kernel: 128 CTAs x 256 threads, all co-resident.
// W_hh (fp16, single plane) lives in SMEM for all 512 steps; h (fp16,
// ping-pong in gmem) streams via 6-stage cp.async; cell state in registers;
// spin grid-barrier between steps.
// ---------------------------------------------------------------------------
__device__ __forceinline__ void load_h_chunk(uint32_t smb, int s, int c, int tid,
                                             const unsigned char* hbase)
{
    uint32_t stg = smb + SM_H + (uint32_t)s * HSTG;
#pragma unroll
    for (int n = 0; n < 2; n++) {
        int i = tid + n * 256;            // 0..511 (16B segs)
        int row = i >> 3;                 // batch 0..63
        int col = i & 7;
        uint32_t d = (uint32_t)row * 144 + (uint32_t)col * 16;
        size_t sg = (size_t)row * 2048 + (size_t)c * 128 + (size_t)col * 16;
        cpasync16(stg + d, hbase + sg);
    }
}

__global__ __launch_bounds__(256, 1)
void persist_kernel(const float* __restrict__ c0, float* __restrict__ out)
{
    extern __shared__ char sm[];
    uint32_t smb = smem_u32(sm);

    const int tid  = threadIdx.x;
    const int wid  = tid >> 5;
    const int lane = tid & 31;
    const int j    = blockIdx.x;
    const int n0   = j * 8;

    const int m0  = (wid & 1) * 16;
    const int bn0 = (wid >> 1) * 16;

    const int mat = lane >> 3;
    const uint32_t aW   = (uint32_t)(m0 + (lane & 7) + ((mat & 1) << 3)) * WPITCH
                        + (uint32_t)(mat >> 1) * 16;
    const uint32_t boff = (uint32_t)(bn0 + (lane & 7) + ((mat >> 1) << 3)) * 144
                        + (uint32_t)(mat & 1) * 16;

    // ---- load W tile into persistent SMEM (once) ----
    {
        const unsigned char* wh = g_whh + (size_t)j * 65536;
#pragma unroll
        for (int n = 0; n < 16; n++) {
            int e = n * 256 + tid;            // 0..4095 (16B units)
            uint32_t d = (uint32_t)(e >> 7) * WPITCH + (uint32_t)(e & 127) * 16;
            cpasync16(smb + SM_W + d, wh + (size_t)e * 16);
        }
        CP_COMMIT();
        CP_WAIT0();
    }

    // ---- cell state in registers: thread owns (b = tid>>2, units eup..eup+1) ----
    const int eb  = tid >> 2;
    const int eup = (tid & 3) * 2;
    float2 creg = *(const float2*)(c0 + (size_t)eb * HH + n0 + eup);
    __syncthreads();

    float* gs = (float*)(sm + SM_H);          // gate exchange overlay (after drain)
    const float* xpb = (const float*)(sm + SM_XP);

    for (int t = 0; t < TT; t++) {
        const unsigned char* hread = g_hb[t & 1];
        unsigned char* hwrite      = g_hb[(t & 1) ^ 1];

        // ---- prologue: chunks 0..4 (+ xproj tile folded into group 0) ----
        load_h_chunk(smb, 0, 0, tid, hread);
        {
            // xproj tile: 64 b x 4 gates x 8 floats -> smem [b][g][8]
#pragma unroll
            for (int n = 0; n < 2; n++) {
                int i = tid * 2 + n;              // 0..511
                int half = i & 1;
                int g = (i >> 1) & 3;
                int b = i >> 3;
                const float* src = g_xproj + ((size_t)t * BB + b) * G4
                                 + (size_t)g * HH + n0 + half * 4;
                cpasync16(smb + SM_XP + (uint32_t)b * 128 + (uint32_t)g * 32
                          + (uint32_t)half * 16, src);
            }
        }
        CP_COMMIT();
#pragma unroll
        for (int c = 1; c < 5; c++) { load_h_chunk(smb, c, c, tid, hread); CP_COMMIT(); }

        float acc[2][4];
#pragma unroll
        for (int i = 0; i < 2; i++)
#pragma unroll
            for (int k = 0; k < 4; k++) acc[i][k] = 0.0f;

        // ---- 16 K-chunks, 6-stage pipeline ----
        int sld = 5;                       // stage for chunk c+5
        for (int c = 0; c < NCHUNK; c++) {
            CP_WAIT4();
            __syncthreads();
            if (c + 5 < NCHUNK) {
                load_h_chunk(smb, sld, c + 5, tid, hread);
                if (++sld == NSTAGE) sld = 0;
            }
            CP_COMMIT();

            const uint32_t stg = smb + SM_H + (uint32_t)(c % NSTAGE) * HSTG;
            const uint32_t wcol = (uint32_t)c * 128;
#pragma unroll
            for (int ks = 0; ks < 4; ks++) {
                const uint32_t kb = (uint32_t)ks * 32;
                uint32_t ah[4], bh[4];
                ldm4(ah, smb + SM_W + aW + wcol + kb);
                ldm4(bh, stg + boff + kb);
                mma16816h(acc[0], ah, bh[0], bh[1]);
                mma16816h(acc[1], ah, bh[2], bh[3]);
            }
        }
        __syncthreads();

        // ---- gate exchange: fragments -> gs[32][68] ----
        {
            const int row0 = m0 + (lane >> 2);
            const int col0 = bn0 + (lane & 3) * 2;
            gs[row0 * 68 + col0]           = acc[0][0];
            gs[row0 * 68 + col0 + 1]       = acc[0][1];
            gs[(row0 + 8) * 68 + col0]     = acc[0][2];
            gs[(row0 + 8) * 68 + col0 + 1] = acc[0][3];
            gs[row0 * 68 + col0 + 8]       = acc[1][0];
            gs[row0 * 68 + col0 + 9]       = acc[1][1];
            gs[(row0 + 8) * 68 + col0 + 8] = acc[1][2];
            gs[(row0 + 8) * 68 + col0 + 9] = acc[1][3];
        }
        __syncthreads();

        // ---- fused epilogue: (b, 2 units) per thread; c in registers ----
        {
            float hv0, hv1;
            {
                const int u = eup;
                float gi = gs[(u)      * 68 + eb] + xpb[eb * 32 + 0 * 8 + u];
                float gf = gs[(8 + u)  * 68 + eb] + xpb[eb * 32 + 1 * 8 + u];
                float gg = gs[(16 + u) * 68 + eb] + xpb[eb * 32 + 2 * 8 + u];
                float go = gs[(24 + u) * 68 + eb] + xpb[eb * 32 + 3 * 8 + u];
                float ii = 1.0f / (1.0f + expf(-gi));
                float ff = 1.0f / (1.0f + expf(-gf));
                float gt = tanhf(gg);
                float oo = 1.0f / (1.0f + expf(-go));
                float cn = ff * creg.x + ii * gt;
                creg.x = cn;
                hv0 = oo * tanhf(cn);
            }
            {
                const int u = eup + 1;
                float gi = gs[(u)      * 68 + eb] + xpb[eb * 32 + 0 * 8 + u];
                float gf = gs[(8 + u)  * 68 + eb] + xpb[eb * 32 + 1 * 8 + u];
                float gg = gs[(16 + u) * 68 + eb] + xpb[eb * 32 + 2 * 8 + u];
                float go = gs[(24 + u) * 68 + eb] + xpb[eb * 32 + 3 * 8 + u];
                float ii = 1.0f / (1.0f + expf(-gi));
                float ff = 1.0f / (1.0f + expf(-gf));
                float gt = tanhf(gg);
                float oo = 1.0f / (1.0f + expf(-go));
                float cn = ff * creg.y + ii * gt;
                creg.y = cn;
                hv1 = oo * tanhf(cn);
            }

            *(float2*)(out + ((size_t)t * BB + eb) * HH + n0 + eup) = make_float2(hv0, hv1);

            __half2 hp = __floats2half2_rn(hv0, hv1);
            *(uint32_t*)(hwrite + (size_t)eb * 2048 + (size_t)(n0 + eup) * 2)
                = *(uint32_t*)&hp;
        }
        __syncthreads();

        // ---- grid barrier (h blob for step t+1 visible before it is read) ----
        if (tid == 0) {
            __threadfence();
            unsigned arrived = atomicAdd(&g_cnt, 1u);
            if (arrived == (unsigned)(t * NCTAP + NCTAP - 1)) {
                __threadfence();
                g_epoch = (unsigned)(t + 1);
            } else {
                while (g_epoch < (unsigned)(t + 1)) __nanosleep(32);
            }
            __threadfence();
        }
        __syncthreads();
    }
}

// ---------------------------------------------------------------------------
// Launch
// ---------------------------------------------------------------------------
extern "C" void kernel_launch(void* const* d_in, const int* in_sizes, int n_in,
                              void* d_out, int out_size)
{
    const float* xs  = (const float*)d_in[0];   // [T,B,IN]
    const float* h0  = (const float*)d_in[1];   // [B,H]
    const float* c0  = (const float*)d_in[2];   // [B,H]
    const float* Wih = (const float*)d_in[3];   // [4H,IN]
    const float* Whh = (const float*)d_in[4];   // [4H,H]
    const float* bih = (const float*)d_in[5];   // [4H]
    const float* bhh = (const float*)d_in[6];   // [4H]
    float* out = (float*)d_out;                 // [T,B,H]

    (void)in_sizes; (void)n_in; (void)out_size;

    cudaFuncSetAttribute(persist_kernel,  cudaFuncAttributeMaxDynamicSharedMemorySize, SMEM_REQ);
    cudaFuncSetAttribute(xprojmma_kernel, cudaFuncAttributeMaxDynamicSharedMemorySize, XP_SMEM);

    prep_xh_kernel<<<8192, 256>>>(xs);
    prep_wih_kernel<<<1024, 256>>>(Wih);
    prep_whh_kernel<<<2048, 256>>>(Whh);
    init_h_kernel<<<32, 256>>>(h0);
    reset_bar_kernel<<<1, 1>>>();

    xprojmma_kernel<<<dim3(32, 256), 256, XP_SMEM>>>(bih, bhh);

    persist_kernel<<<NCTAP, 256, SMEM_REQ>>>(c0, out);
}